// round 9
// baseline (speedup 1.0000x reference)
#include <cuda_runtime.h>

typedef unsigned long long u64;

#define T_ 1132
#define B_ 128
#define L_ 100
#define TH_ 14716
#define C_ 10
#define NW_ 16           // warps per layer-CTA
#define THREADS_ 512     // 4 lanes (j-split) per batch element

// Double-buffered layer activations + per-(t,warp) progress flags.
__device__ float g_buf[2][T_][B_][16];   // [parity][t][b][padded H]
__device__ int   g_prog[T_][NW_];        // layers finished (t, warp-slice)

__device__ __forceinline__ int ld_acq(const int* p) {
    int v;
    asm volatile("ld.acquire.gpu.global.b32 %0, [%1];" : "=r"(v) : "l"(p) : "memory");
    return v;
}
__device__ __forceinline__ void st_rel(int* p, int v) {
    asm volatile("st.release.gpu.global.b32 [%0], %1;" :: "l"(p), "r"(v) : "memory");
}

__device__ __forceinline__ u64 pack2(float lo, float hi) {
    u64 d; asm("mov.b64 %0, {%1, %2};" : "=l"(d) : "f"(lo), "f"(hi)); return d;
}
__device__ __forceinline__ void unpack2(u64 v, float& lo, float& hi) {
    asm("mov.b64 {%0, %1}, %2;" : "=f"(lo), "=f"(hi) : "l"(v));
}
// two independent fp32 FMA lanes (FFMA2) — PTX-only instruction
__device__ __forceinline__ u64 fma2(u64 a, u64 b, u64 c) {
    u64 d; asm("fma.rn.f32x2 %0, %1, %2, %3;" : "=l"(d) : "l"(a), "l"(b), "l"(c)); return d;
}
__device__ __forceinline__ u64 add2(u64 a, u64 b) {
    u64 d; asm("add.rn.f32x2 %0, %1, %2;" : "=l"(d) : "l"(a), "l"(b)); return d;
}

__device__ __forceinline__ float sigf(float x) {
    return __fdividef(1.0f, 1.0f + __expf(-x));
}
// tanh via sigmoid identity: 2/(1+e^-2x) - 1 (clean saturation, no NaN)
__device__ __forceinline__ float tanh_f(float x) {
    return __fdividef(2.0f, 1.0f + __expf(-2.0f * x)) - 1.0f;
}

__global__ void k_reset() {
    int i = blockIdx.x * blockDim.x + threadIdx.x;
    if (i < T_ * NW_) ((int*)g_prog)[i] = 0;
}

// One CTA per layer. 4 lanes per batch (tid = 4*b_local + q); lane q owns
// hidden units j = 4q+jl, jl in [0,4) (units padded 13->16, pads inert).
// Weight layout s_w[side][jl][kk][q]: the 4 lanes of a group read CONSECUTIVE
// float4s -> 64B span, banks 0-15, conflict-free broadcast (fixes R4's 2-way
// conflict). Full x/h per lane so gates need no cross-lane reduction; h is
// all-gathered with 13 width-4 shuffles. 1-step prefetch hides the handoff.
__global__ __launch_bounds__(THREADS_, 1) void k_lstm(
    const float* __restrict__ input,
    const float* __restrict__ w_ih, const float* __restrict__ w_hh,
    const float* __restrict__ b_ih, const float* __restrict__ b_hh)
{
    // s_w[side][jl][kk][q] = float4 {A[2kk], B[2kk], A[2kk+1], B[2kk+1]} for
    // unit j=4q+jl.  side0: x,(i,f)  side1: x,(g,o)  side2: h,(i,f)  side3: h,(g,o)
    __shared__ __align__(16) float4 s_w[4][4][7][4];
    __shared__ __align__(16) float  s_b[4][4][4];   // [jl][q][gate] {bi,bf,bg,bo}

    const int l   = blockIdx.x;
    const int tid = threadIdx.x;
    const int q   = tid & 3;        // lane within batch group
    const int b   = tid >> 2;       // batch element
    const int w   = tid >> 5;       // warp id

    // --- load + pack weights (zeros for j>=13 or k>=13) ---
    for (int i = tid; i < 4 * 4 * 7 * 4 * 4; i += THREADS_) {
        int side = i / 448, r = i % 448;
        int jl = r / 112,  r2 = r % 112;
        int kk = r2 / 16,  r3 = r2 % 16;
        int qq = r3 >> 2,  e = r3 & 3;
        int k = 2 * kk + (e >> 1);
        int gate = ((side & 1) ? 2 : 0) + (e & 1);
        int j = 4 * qq + jl;
        const float* src = (side < 2) ? w_ih : w_hh;
        float v = (j < 13 && k < 13) ? src[(l * 52 + gate * 13 + j) * 13 + k] : 0.0f;
        ((float*)s_w)[i] = v;
    }
    for (int i = tid; i < 64; i += THREADS_) {
        int jl = i >> 4, qq = (i >> 2) & 3, g = i & 3;
        int j = 4 * qq + jl;
        s_b[jl][qq][g] = (j < 13) ? (b_ih[l * 52 + g * 13 + j] + b_hh[l * 52 + g * 13 + j]) : 0.0f;
    }
    __syncthreads();

    // --- per-thread state ---
    u64 xd[13], hd[13];             // full x/h, f32x2-replicated
    float c[4], myh[4];             // owned hidden units
    #pragma unroll
    for (int k = 0; k < 13; k++) { xd[k] = 0ull; hd[k] = 0ull; }
    #pragma unroll
    for (int j = 0; j < 4; j++) { c[j] = 0.0f; myh[j] = 0.0f; }

    const int wp = l & 1;
    const int rp = wp ^ 1;

    // ---- preload x(0) ----
    if (l == 0) {
        const float* ir = &input[(b * T_ + 0) * 13];
        #pragma unroll
        for (int k = 0; k < 13; k++) { float v = ir[k]; xd[k] = pack2(v, v); }
    } else {
        while (ld_acq(&g_prog[0][w]) < l) { }
        const float4* src = (const float4*)&g_buf[rp][0][b][0];
        float4 v0 = src[0], v1 = src[1], v2 = src[2], v3 = src[3];
        xd[0]  = pack2(v0.x, v0.x); xd[1]  = pack2(v0.y, v0.y);
        xd[2]  = pack2(v0.z, v0.z); xd[3]  = pack2(v0.w, v0.w);
        xd[4]  = pack2(v1.x, v1.x); xd[5]  = pack2(v1.y, v1.y);
        xd[6]  = pack2(v1.z, v1.z); xd[7]  = pack2(v1.w, v1.w);
        xd[8]  = pack2(v2.x, v2.x); xd[9]  = pack2(v2.y, v2.y);
        xd[10] = pack2(v2.z, v2.z); xd[11] = pack2(v2.w, v2.w);
        xd[12] = pack2(v3.x, v3.x);
    }

    for (int t = 0; t < T_; t++) {
        const bool pf = (t + 1 < T_);
        int fv = 0;
        float4 n0, n1, n2, n3;
        float  nin[13];

        // ---- blind prefetch of next cell's input (overlaps compute) ----
        if (pf) {
            if (l == 0) {
                const float* ir = &input[(b * T_ + t + 1) * 13];
                #pragma unroll
                for (int k = 0; k < 13; k++) nin[k] = ir[k];
            } else {
                fv = ld_acq(&g_prog[t + 1][w]);   // acquire orders loads below
                const float4* src = (const float4*)&g_buf[rp][t + 1][b][0];
                n0 = src[0]; n1 = src[1]; n2 = src[2]; n3 = src[3];
            }
        }

        // ---- gates + state update for my 4 owned units ----
        #pragma unroll
        for (int jl = 0; jl < 4; jl++) {
            const u64* pb = (const u64*)&s_b[jl][q][0];   // lane-consecutive 16B
            u64 axif = pb[0];
            u64 axgo = pb[1];
            u64 ahif = 0ull, ahgo = 0ull;
            #pragma unroll
            for (int kk = 0; kk < 7; kk++) {
                ulonglong2 wxif = *(const ulonglong2*)&s_w[0][jl][kk][q];
                ulonglong2 wxgo = *(const ulonglong2*)&s_w[1][jl][kk][q];
                ulonglong2 whif = *(const ulonglong2*)&s_w[2][jl][kk][q];
                ulonglong2 whgo = *(const ulonglong2*)&s_w[3][jl][kk][q];
                int k0 = 2 * kk, k1 = 2 * kk + 1;
                u64 x0 = xd[k0], h0 = hd[k0];
                u64 x1 = (k1 < 13) ? xd[k1] : 0ull;
                u64 h1 = (k1 < 13) ? hd[k1] : 0ull;
                axif = fma2(wxif.x, x0, axif);
                axgo = fma2(wxgo.x, x0, axgo);
                ahif = fma2(whif.x, h0, ahif);
                ahgo = fma2(whgo.x, h0, ahgo);
                axif = fma2(wxif.y, x1, axif);
                axgo = fma2(wxgo.y, x1, axgo);
                ahif = fma2(whif.y, h1, ahif);
                ahgo = fma2(whgo.y, h1, ahgo);
            }
            u64 gif = add2(axif, ahif);
            u64 ggo = add2(axgo, ahgo);
            float ai, af, ag, ao;
            unpack2(gif, ai, af);
            unpack2(ggo, ag, ao);
            float ig = sigf(ai), fg = sigf(af), gv = tanh_f(ag), og = sigf(ao);
            float cn = fmaf(fg, c[jl], ig * gv);
            c[jl]   = cn;
            myh[jl] = og * tanh_f(cn);
        }

        // ---- all-gather 13 h values within the 4-lane batch group ----
        // unit j = 4*(j>>2) + (j&3): owner lane j>>2, register slot j&3
        float hv[13];
        #pragma unroll
        for (int j = 0; j < 13; j++) {
            hv[j] = __shfl_sync(0xFFFFFFFFu, myh[j & 3], j >> 2, 4);
            hd[j] = pack2(hv[j], hv[j]);
        }

        // ---- publish: lane q writes its 16B quarter (coalesced 64B/batch) ----
        {
            float4* dst = (float4*)&g_buf[wp][t][b][0];
            float4 out4;
            if      (q == 0) out4 = make_float4(hv[0],  hv[1],  hv[2],  hv[3]);
            else if (q == 1) out4 = make_float4(hv[4],  hv[5],  hv[6],  hv[7]);
            else if (q == 2) out4 = make_float4(hv[8],  hv[9],  hv[10], hv[11]);
            else             out4 = make_float4(hv[12], 0.0f,   0.0f,   0.0f);
            dst[q] = out4;
        }

        __syncwarp();
        if ((tid & 31) == 0) st_rel(&g_prog[t][w], l + 1);

        // ---- validate prefetch; fall back to poll + reload on miss ----
        if (pf) {
            if (l == 0) {
                #pragma unroll
                for (int k = 0; k < 13; k++) xd[k] = pack2(nin[k], nin[k]);
            } else {
                if (fv < l) {
                    while (ld_acq(&g_prog[t + 1][w]) < l) { }
                    const float4* src = (const float4*)&g_buf[rp][t + 1][b][0];
                    n0 = src[0]; n1 = src[1]; n2 = src[2]; n3 = src[3];
                }
                xd[0]  = pack2(n0.x, n0.x); xd[1]  = pack2(n0.y, n0.y);
                xd[2]  = pack2(n0.z, n0.z); xd[3]  = pack2(n0.w, n0.w);
                xd[4]  = pack2(n1.x, n1.x); xd[5]  = pack2(n1.y, n1.y);
                xd[6]  = pack2(n1.z, n1.z); xd[7]  = pack2(n1.w, n1.w);
                xd[8]  = pack2(n2.x, n2.x); xd[9]  = pack2(n2.y, n2.y);
                xd[10] = pack2(n2.z, n2.z); xd[11] = pack2(n2.w, n2.w);
                xd[12] = pack2(n3.x, n3.x);
            }
        }
    }
}

// Final linear + softmax. One CTA per batch element.
__global__ __launch_bounds__(256) void k_cls(
    const float* __restrict__ w_lin, const float* __restrict__ b_lin,
    float* __restrict__ out)
{
    const int bb  = blockIdx.x;
    const int tid = threadIdx.x;

    float acc[C_];
    #pragma unroll
    for (int cc = 0; cc < C_; cc++) acc[cc] = 0.0f;

    for (int t = tid; t < T_; t += 256) {
        const float* xr = &g_buf[1][t][bb][0];   // layer 99 writes parity 1
        float xv[13];
        #pragma unroll
        for (int k = 0; k < 13; k++) xv[k] = xr[k];
        #pragma unroll
        for (int cc = 0; cc < C_; cc++) {
            const float* wr = &w_lin[cc * TH_ + t * 13];
            float a = acc[cc];
            #pragma unroll
            for (int k = 0; k < 13; k++) a = fmaf(xv[k], wr[k], a);
            acc[cc] = a;
        }
    }

    __shared__ float red[256];
    __shared__ float lg[C_];
    #pragma unroll 1
    for (int cc = 0; cc < C_; cc++) {
        red[tid] = acc[cc];
        __syncthreads();
        for (int st = 128; st > 0; st >>= 1) {
            if (tid < st) red[tid] += red[tid + st];
            __syncthreads();
        }
        if (tid == 0) lg[cc] = red[0] + b_lin[cc];
        __syncthreads();
    }

    if (tid == 0) {
        float m = lg[0];
        #pragma unroll
        for (int cc = 1; cc < C_; cc++) m = fmaxf(m, lg[cc]);
        float e[C_];
        float ssum = 0.0f;
        #pragma unroll
        for (int cc = 0; cc < C_; cc++) { e[cc] = __expf(lg[cc] - m); ssum += e[cc]; }
        float inv = __fdividef(1.0f, ssum);
        #pragma unroll
        for (int cc = 0; cc < C_; cc++) out[bb * C_ + cc] = e[cc] * inv;
    }
}

extern "C" void kernel_launch(void* const* d_in, const int* in_sizes, int n_in,
                              void* d_out, int out_size)
{
    const float* input = (const float*)d_in[0];
    const float* w_ih  = (const float*)d_in[1];
    const float* w_hh  = (const float*)d_in[2];
    const float* b_ih  = (const float*)d_in[3];
    const float* b_hh  = (const float*)d_in[4];
    const float* w_lin = (const float*)d_in[5];
    const float* b_lin = (const float*)d_in[6];

    // Flags zero at module load; k_reset (last) re-zeros after each call so
    // every graph replay starts clean. k_lstm first keeps it in ncu's slot.
    k_lstm<<<L_, THREADS_>>>(input, w_ih, w_hh, b_ih, b_hh);
    k_cls<<<B_, 256>>>(w_lin, b_lin, (float*)d_out);
    k_reset<<<(T_ * NW_ + 255) / 256, 256>>>();
}

// round 11
// speedup vs baseline: 1.4907x; 1.4907x over previous
#include <cuda_runtime.h>

typedef unsigned long long u64;

#define T_ 1132
#define B_ 128
#define L_ 100
#define TH_ 14716
#define C_ 10
#define NW_ 8            // warps per layer-CTA
#define THREADS_ 256     // 2 lanes (j-split) per batch element
#define CS_ 4            // handoff chunk size (timesteps per flag)
#define NCH_ 283         // T_ / CS_

// Double-buffered layer activations + per-(chunk,warp) progress flags.
__device__ float g_buf[2][T_][B_][16];   // [parity][t][b][padded H]
__device__ int   g_prog[NCH_][NW_];      // layers that finished chunk (c, warp)

__device__ __forceinline__ int ld_acq(const int* p) {
    int v;
    asm volatile("ld.acquire.gpu.global.b32 %0, [%1];" : "=r"(v) : "l"(p) : "memory");
    return v;
}
__device__ __forceinline__ void st_rel(int* p, int v) {
    asm volatile("st.release.gpu.global.b32 [%0], %1;" :: "l"(p), "r"(v) : "memory");
}

__device__ __forceinline__ u64 pack2(float lo, float hi) {
    u64 d; asm("mov.b64 %0, {%1, %2};" : "=l"(d) : "f"(lo), "f"(hi)); return d;
}
__device__ __forceinline__ void unpack2(u64 v, float& lo, float& hi) {
    asm("mov.b64 {%0, %1}, %2;" : "=f"(lo), "=f"(hi) : "l"(v));
}
// two independent fp32 FMA lanes (FFMA2) — PTX-only instruction
__device__ __forceinline__ u64 fma2(u64 a, u64 b, u64 c) {
    u64 d; asm("fma.rn.f32x2 %0, %1, %2, %3;" : "=l"(d) : "l"(a), "l"(b), "l"(c)); return d;
}
__device__ __forceinline__ u64 add2(u64 a, u64 b) {
    u64 d; asm("add.rn.f32x2 %0, %1, %2;" : "=l"(d) : "l"(a), "l"(b)); return d;
}

__device__ __forceinline__ float sigf(float x) {
    return __fdividef(1.0f, 1.0f + __expf(-x));
}
// tanh via sigmoid identity: 2/(1+e^-2x) - 1 (clean saturation, no NaN)
__device__ __forceinline__ float tanh_f(float x) {
    return __fdividef(2.0f, 1.0f + __expf(-2.0f * x)) - 1.0f;
}

__global__ void k_reset() {
    int i = blockIdx.x * blockDim.x + threadIdx.x;
    if (i < NCH_ * NW_) ((int*)g_prog)[i] = 0;
}

// One CTA per layer. Lane pair per batch (tid = 2*b_local + p); lane parity p
// owns hidden units j in [7p, 7p+7) (padded to 14, lane 1's 7th inert).
// Cross-layer handoff is CHUNKED: the producer publishes one release-flag per
// CS_=4 timesteps, so the consumer self-stabilizes at ~4 steps of slack and
// the per-cell blind prefetch of x(t+1) nearly always hits (L2 trip hidden).
__global__ __launch_bounds__(THREADS_, 1) void k_lstm(
    const float* __restrict__ input,
    const float* __restrict__ w_ih, const float* __restrict__ w_hh,
    const float* __restrict__ b_ih, const float* __restrict__ b_hh)
{
    // Packed weights, j padded to 14:
    // s_w[side][j][kk] = {A[2kk], B[2kk], A[2kk+1], B[2kk+1]}
    //   side0: x,(i,f)  side1: x,(g,o)  side2: h,(i,f)  side3: h,(g,o)
    __shared__ __align__(16) float4 s_w[4][14][7];
    __shared__ __align__(16) float  s_b[14][4];   // {bi, bf, bg, bo} per j

    const int l   = blockIdx.x;
    const int tid = threadIdx.x;
    const int p   = tid & 1;        // j-half owner
    const int b   = tid >> 1;       // batch element
    const int w   = tid >> 5;       // warp id

    // --- load + pack weights (zeros for j>=13 or k>=13) ---
    for (int i = tid; i < 4 * 14 * 28; i += THREADS_) {
        int side = i / 392, r = i % 392;
        int j = r / 28,  s2 = r % 28;
        int kk = s2 >> 2, e = s2 & 3;
        int k = 2 * kk + (e >> 1);
        int gate = ((side & 1) ? 2 : 0) + (e & 1);
        const float* src = (side < 2) ? w_ih : w_hh;
        float v = (j < 13 && k < 13) ? src[(l * 52 + gate * 13 + j) * 13 + k] : 0.0f;
        ((float*)s_w)[i] = v;
    }
    for (int i = tid; i < 56; i += THREADS_) {
        int g = i & 3, j = i >> 2;
        s_b[j][g] = (j < 13) ? (b_ih[l * 52 + g * 13 + j] + b_hh[l * 52 + g * 13 + j]) : 0.0f;
    }
    __syncthreads();

    // --- per-thread state ---
    u64 xd[13], hd[13];             // full x/h, f32x2-replicated
    float c[7], myh[7];             // owned hidden units
    #pragma unroll
    for (int k = 0; k < 13; k++) { xd[k] = 0ull; hd[k] = 0ull; }
    #pragma unroll
    for (int j = 0; j < 7; j++) { c[j] = 0.0f; myh[j] = 0.0f; }

    const int wp = l & 1;
    const int rp = wp ^ 1;
    const u64* pb = (const u64*)s_b;
    const int jbase = 7 * p;

    // ---- preload x(0) (requires producer's chunk 0 fully published) ----
    if (l == 0) {
        const float* ir = &input[(b * T_ + 0) * 13];
        #pragma unroll
        for (int k = 0; k < 13; k++) { float v = ir[k]; xd[k] = pack2(v, v); }
    } else {
        while (ld_acq(&g_prog[0][w]) < l) { }
        const float4* src = (const float4*)&g_buf[rp][0][b][0];
        float4 v0 = src[0], v1 = src[1], v2 = src[2], v3 = src[3];
        xd[0]  = pack2(v0.x, v0.x); xd[1]  = pack2(v0.y, v0.y);
        xd[2]  = pack2(v0.z, v0.z); xd[3]  = pack2(v0.w, v0.w);
        xd[4]  = pack2(v1.x, v1.x); xd[5]  = pack2(v1.y, v1.y);
        xd[6]  = pack2(v1.z, v1.z); xd[7]  = pack2(v1.w, v1.w);
        xd[8]  = pack2(v2.x, v2.x); xd[9]  = pack2(v2.y, v2.y);
        xd[10] = pack2(v2.z, v2.z); xd[11] = pack2(v2.w, v2.w);
        xd[12] = pack2(v3.x, v3.x);
    }

    for (int t = 0; t < T_; t++) {
        const bool pf = (t + 1 < T_);
        int fv = 0;
        float4 n0, n1, n2, n3;
        float  nin[13];

        // ---- blind prefetch of next cell's input (overlaps compute) ----
        if (pf) {
            if (l == 0) {
                const float* ir = &input[(b * T_ + t + 1) * 13];
                #pragma unroll
                for (int k = 0; k < 13; k++) nin[k] = ir[k];
            } else {
                fv = ld_acq(&g_prog[(t + 1) >> 2][w]);  // chunk flag; acquire orders loads
                const float4* src = (const float4*)&g_buf[rp][t + 1][b][0];
                n0 = src[0]; n1 = src[1]; n2 = src[2]; n3 = src[3];
            }
        }

        // ---- gates + state update for my 7 owned units ----
        #pragma unroll
        for (int jl = 0; jl < 7; jl++) {
            const int jj = jbase + jl;           // p=1, jl=6 -> jj=13 (inert pad)
            u64 axif = pb[jj * 2];
            u64 axgo = pb[jj * 2 + 1];
            u64 ahif = 0ull, ahgo = 0ull;
            #pragma unroll
            for (int kk = 0; kk < 7; kk++) {
                ulonglong2 wxif = *(const ulonglong2*)&s_w[0][jj][kk];
                ulonglong2 wxgo = *(const ulonglong2*)&s_w[1][jj][kk];
                ulonglong2 whif = *(const ulonglong2*)&s_w[2][jj][kk];
                ulonglong2 whgo = *(const ulonglong2*)&s_w[3][jj][kk];
                int k0 = 2 * kk, k1 = 2 * kk + 1;
                u64 x0 = xd[k0], h0 = hd[k0];
                u64 x1 = (k1 < 13) ? xd[k1] : 0ull;
                u64 h1 = (k1 < 13) ? hd[k1] : 0ull;
                axif = fma2(wxif.x, x0, axif);
                axgo = fma2(wxgo.x, x0, axgo);
                ahif = fma2(whif.x, h0, ahif);
                ahgo = fma2(whgo.x, h0, ahgo);
                axif = fma2(wxif.y, x1, axif);
                axgo = fma2(wxgo.y, x1, axgo);
                ahif = fma2(whif.y, h1, ahif);
                ahgo = fma2(whgo.y, h1, ahgo);
            }
            u64 gif = add2(axif, ahif);
            u64 ggo = add2(axgo, ahgo);
            float ai, af, ag, ao;
            unpack2(gif, ai, af);
            unpack2(ggo, ag, ao);
            float ig = sigf(ai), fg = sigf(af), gv = tanh_f(ag), og = sigf(ao);
            float cn = fmaf(fg, c[jl], ig * gv);
            c[jl]   = cn;
            myh[jl] = og * tanh_f(cn);
        }

        // ---- all-gather 13 h values within the lane pair ----
        float hv[13];
        #pragma unroll
        for (int j = 0; j < 13; j++) {
            const int owner = (j < 7) ? 0 : 1;
            const int slot  = (j < 7) ? j : j - 7;
            hv[j] = __shfl_sync(0xFFFFFFFFu, myh[slot], owner, 2);
            hd[j] = pack2(hv[j], hv[j]);
        }

        // ---- publish my half (two 16B stores; 64B total per batch) ----
        float4* dst = (float4*)&g_buf[wp][t][b][0];
        if (p == 0) {
            dst[0] = make_float4(hv[0], hv[1], hv[2], hv[3]);
            dst[1] = make_float4(hv[4], hv[5], hv[6], hv[7]);
        } else {
            dst[2] = make_float4(hv[8], hv[9], hv[10], hv[11]);
            dst[3] = make_float4(hv[12], 0.0f, 0.0f, 0.0f);
        }

        // ---- chunk-granular release: one strong store per CS_ cells ----
        if ((t & (CS_ - 1)) == CS_ - 1) {
            __syncwarp();
            if ((tid & 31) == 0) st_rel(&g_prog[t >> 2][w], l + 1);
        }

        // ---- validate prefetch; fall back to poll + reload on miss ----
        if (pf) {
            if (l == 0) {
                #pragma unroll
                for (int k = 0; k < 13; k++) xd[k] = pack2(nin[k], nin[k]);
            } else {
                if (fv < l) {
                    while (ld_acq(&g_prog[(t + 1) >> 2][w]) < l) { }
                    const float4* src = (const float4*)&g_buf[rp][t + 1][b][0];
                    n0 = src[0]; n1 = src[1]; n2 = src[2]; n3 = src[3];
                }
                xd[0]  = pack2(n0.x, n0.x); xd[1]  = pack2(n0.y, n0.y);
                xd[2]  = pack2(n0.z, n0.z); xd[3]  = pack2(n0.w, n0.w);
                xd[4]  = pack2(n1.x, n1.x); xd[5]  = pack2(n1.y, n1.y);
                xd[6]  = pack2(n1.z, n1.z); xd[7]  = pack2(n1.w, n1.w);
                xd[8]  = pack2(n2.x, n2.x); xd[9]  = pack2(n2.y, n2.y);
                xd[10] = pack2(n2.z, n2.z); xd[11] = pack2(n2.w, n2.w);
                xd[12] = pack2(n3.x, n3.x);
            }
        }
    }
}

// Final linear + softmax. One CTA per batch element.
__global__ __launch_bounds__(256) void k_cls(
    const float* __restrict__ w_lin, const float* __restrict__ b_lin,
    float* __restrict__ out)
{
    const int bb  = blockIdx.x;
    const int tid = threadIdx.x;

    float acc[C_];
    #pragma unroll
    for (int cc = 0; cc < C_; cc++) acc[cc] = 0.0f;

    for (int t = tid; t < T_; t += 256) {
        const float* xr = &g_buf[1][t][bb][0];   // layer 99 writes parity 1
        float xv[13];
        #pragma unroll
        for (int k = 0; k < 13; k++) xv[k] = xr[k];
        #pragma unroll
        for (int cc = 0; cc < C_; cc++) {
            const float* wr = &w_lin[cc * TH_ + t * 13];
            float a = acc[cc];
            #pragma unroll
            for (int k = 0; k < 13; k++) a = fmaf(xv[k], wr[k], a);
            acc[cc] = a;
        }
    }

    __shared__ float red[256];
    __shared__ float lg[C_];
    #pragma unroll 1
    for (int cc = 0; cc < C_; cc++) {
        red[tid] = acc[cc];
        __syncthreads();
        for (int st = 128; st > 0; st >>= 1) {
            if (tid < st) red[tid] += red[tid + st];
            __syncthreads();
        }
        if (tid == 0) lg[cc] = red[0] + b_lin[cc];
        __syncthreads();
    }

    if (tid == 0) {
        float m = lg[0];
        #pragma unroll
        for (int cc = 1; cc < C_; cc++) m = fmaxf(m, lg[cc]);
        float e[C_];
        float ssum = 0.0f;
        #pragma unroll
        for (int cc = 0; cc < C_; cc++) { e[cc] = __expf(lg[cc] - m); ssum += e[cc]; }
        float inv = __fdividef(1.0f, ssum);
        #pragma unroll
        for (int cc = 0; cc < C_; cc++) out[bb * C_ + cc] = e[cc] * inv;
    }
}

extern "C" void kernel_launch(void* const* d_in, const int* in_sizes, int n_in,
                              void* d_out, int out_size)
{
    const float* input = (const float*)d_in[0];
    const float* w_ih  = (const float*)d_in[1];
    const float* w_hh  = (const float*)d_in[2];
    const float* b_ih  = (const float*)d_in[3];
    const float* b_hh  = (const float*)d_in[4];
    const float* w_lin = (const float*)d_in[5];
    const float* b_lin = (const float*)d_in[6];

    // Flags zero at module load; k_reset (last) re-zeros after each call so
    // every graph replay starts clean. k_lstm first keeps it in ncu's slot.
    k_lstm<<<L_, THREADS_>>>(input, w_ih, w_hh, b_ih, b_hh);
    k_cls<<<B_, 256>>>(w_lin, b_lin, (float*)d_out);
    k_reset<<<(NCH_ * NW_ + 255) / 256, 256>>>();
}